// round 4
// baseline (speedup 1.0000x reference)
#include <cuda_runtime.h>
#include <math.h>
#include <float.h>

// Problem constants
#define NS 25      // support count (WAY*SHOT)
#define NQ 75      // query count (WAY*QUERY_SHOT)
#define DD 640     // feature dim
#define MM 25      // M (inner dim)
#define NCHUNK 5   // d-chunks of 128

// Scratch (device globals; zero at load, restored to zero by each launch)
__device__ float g_P[NQ * NS * DD];   // P[q][s][d] = sum_m S[s,d,m]*W[s,q,m]
__device__ float g_l2[NQ * NS];       // raw sum_d (p-r)^2, [q][s]
__device__ int   g_cnt[NQ];           // softmax tickets per q
__device__ int   g_prod[NCHUNK];      // producer-done count per d-chunk
__device__ int   g_cons[NCHUNK];      // consumer-done count per d-chunk

struct SmemProd {                      // producer staging (21.2 KB)
    float W[MM][80];                   // [m][q], q padded to 80
    float S[MM][132];                  // [m][d], 128 d (+pad)
};
struct SmemCons {                      // consumer staging (16.8 KB)
    float W[MM][36];                   // [m][s], s padded to 32
    float Q[MM][132];                  // [m][d]
};

// ---------------------------------------------------------------------------
// Single fused kernel. grid = (5 d-chunks, 75 q), block = 256 (8 warps).
// Blocks with q < NS also act as producer for s = q on their d-chunk.
// ---------------------------------------------------------------------------
__global__ __launch_bounds__(256, 3) void fused_kernel(
        const float* __restrict__ fm, const float* __restrict__ w2,
        const float* __restrict__ scale, float* __restrict__ out) {
    const int d0i = blockIdx.x;
    const int d0  = d0i * 128;
    const int q   = blockIdx.y;
    const int tid  = threadIdx.x;
    const int lane = tid & 31;
    const int warp = tid >> 5;

    __shared__ __align__(16) union { SmemProd p; SmemCons c; } sm;
    __shared__ int s_last;

    // ===================== Producer role (q < NS, s = q) ===================
    if (q < NS) {
        const int s = q;
        for (int idx = tid; idx < NQ * MM; idx += 256) {
            int qq = idx / MM, m = idx - qq * MM;
            sm.p.W[m][qq] = w2[s * (NQ * MM) + idx];
        }
        for (int idx = tid; idx < 5 * MM; idx += 256) {    // zero-pad q=75..79
            int m = idx % MM, qq = NQ + idx / MM;
            sm.p.W[m][qq] = 0.0f;
        }
        for (int idx = tid; idx < 128 * MM; idx += 256) {
            int d = idx / MM, m = idx - d * MM;
            sm.p.S[m][d] = fm[s * (DD * MM) + d0 * MM + idx];
        }
        __syncthreads();

        const int qb = warp * 10;   // warp -> q base (0..70)
        float acc[10][4];
#pragma unroll
        for (int j = 0; j < 10; j++)
#pragma unroll
            for (int i = 0; i < 4; i++) acc[j][i] = 0.0f;

#pragma unroll
        for (int m = 0; m < MM; m++) {
            float4 bv = *reinterpret_cast<const float4*>(&sm.p.S[m][lane * 4]);
#pragma unroll
            for (int j = 0; j < 10; j++) {
                float a = sm.p.W[m][qb + j];
                acc[j][0] = fmaf(a, bv.x, acc[j][0]);
                acc[j][1] = fmaf(a, bv.y, acc[j][1]);
                acc[j][2] = fmaf(a, bv.z, acc[j][2]);
                acc[j][3] = fmaf(a, bv.w, acc[j][3]);
            }
        }

#pragma unroll
        for (int j = 0; j < 10; j++) {
            int qq = qb + j;
            if (qq < NQ) {
                float4 v = make_float4(acc[j][0], acc[j][1], acc[j][2], acc[j][3]);
                *reinterpret_cast<float4*>(
                    &g_P[(qq * NS + s) * DD + d0 + lane * 4]) = v;
            }
        }
        __threadfence();            // release: P stores visible before flag
        __syncthreads();            // all threads' stores issued + smem reads done
        if (tid == 0) atomicAdd(&g_prod[d0i], 1);
        __syncthreads();            // safe to reuse smem union
    }

    // ===================== Consumer role (all 375 blocks) ===================
    for (int idx = tid; idx < NS * MM; idx += 256) {
        int sI = idx / MM, m = idx - sI * MM;
        sm.c.W[m][sI] = w2[(sI * NQ + q) * MM + m];
    }
    for (int idx = tid; idx < 7 * MM; idx += 256) {        // zero-pad s=25..31
        int m = idx % MM, sI = NS + idx / MM;
        sm.c.W[m][sI] = 0.0f;
    }
    for (int idx = tid; idx < 128 * MM; idx += 256) {
        int d = idx / MM, m = idx - d * MM;
        sm.c.Q[m][d] = fm[(NS + q) * (DD * MM) + d0 * MM + idx];
    }
    __syncthreads();

    const int sb = warp * 4;        // warp -> s base (0..28)

    float acc[4][4];
#pragma unroll
    for (int j = 0; j < 4; j++)
#pragma unroll
        for (int i = 0; i < 4; i++) acc[j][i] = 0.0f;

#pragma unroll
    for (int m = 0; m < MM; m++) {
        float4 bv = *reinterpret_cast<const float4*>(&sm.c.Q[m][lane * 4]);
        float4 av = *reinterpret_cast<const float4*>(&sm.c.W[m][sb]);
        acc[0][0] = fmaf(av.x, bv.x, acc[0][0]);
        acc[0][1] = fmaf(av.x, bv.y, acc[0][1]);
        acc[0][2] = fmaf(av.x, bv.z, acc[0][2]);
        acc[0][3] = fmaf(av.x, bv.w, acc[0][3]);
        acc[1][0] = fmaf(av.y, bv.x, acc[1][0]);
        acc[1][1] = fmaf(av.y, bv.y, acc[1][1]);
        acc[1][2] = fmaf(av.y, bv.z, acc[1][2]);
        acc[1][3] = fmaf(av.y, bv.w, acc[1][3]);
        acc[2][0] = fmaf(av.z, bv.x, acc[2][0]);
        acc[2][1] = fmaf(av.z, bv.y, acc[2][1]);
        acc[2][2] = fmaf(av.z, bv.z, acc[2][2]);
        acc[2][3] = fmaf(av.z, bv.w, acc[2][3]);
        acc[3][0] = fmaf(av.w, bv.x, acc[3][0]);
        acc[3][1] = fmaf(av.w, bv.y, acc[3][1]);
        acc[3][2] = fmaf(av.w, bv.z, acc[3][2]);
        acc[3][3] = fmaf(av.w, bv.w, acc[3][3]);
    }

    // Wait until all 25 producers for this d-chunk have published P.
    if (tid == 0) {
        while (*(volatile int*)&g_prod[d0i] < NS) __nanosleep(32);
    }
    __syncthreads();
    __threadfence();                // acquire: P loads see producer stores

    // Epilogue: (r - p)^2, reduce 4 local + 32 lanes, atomic add into g_l2.
#pragma unroll
    for (int j = 0; j < 4; j++) {
        int   s    = sb + j;
        float part = 0.0f;
        if (s < NS) {
            float4 pv = *reinterpret_cast<const float4*>(
                &g_P[(q * NS + s) * DD + d0 + lane * 4]);
            float t0 = acc[j][0] - pv.x;
            float t1 = acc[j][1] - pv.y;
            float t2 = acc[j][2] - pv.z;
            float t3 = acc[j][3] - pv.w;
            part = t0 * t0 + t1 * t1 + t2 * t2 + t3 * t3;
        }
#pragma unroll
        for (int off = 16; off > 0; off >>= 1)
            part += __shfl_down_sync(0xffffffffu, part, off);
        if (lane == 0 && s < NS)
            atomicAdd(&g_l2[q * NS + s], part);
    }

    __threadfence();
    __syncthreads();
    if (tid == 0) {
        // chunk bookkeeping: last consumer of this d-chunk resets its flags
        int oc = atomicAdd(&g_cons[d0i], 1);
        if (oc == NQ - 1) { g_prod[d0i] = 0; g_cons[d0i] = 0; }
        // softmax ticket: 5th chunk-block for this q runs the softmax
        s_last = (atomicAdd(&g_cnt[q], 1) == NCHUNK - 1) ? 1 : 0;
    }
    __syncthreads();

    if (s_last && tid < 32) {
        __threadfence();            // acquire: all g_l2 adds for this q visible
        const float c = -scale[0] / 312500.0f;   // 1/(M^2 * G*Q*Q*SHOT)
        float raw   = (tid < NS) ? __ldcg(&g_l2[q * NS + tid]) : 0.0f;
        float logit = (tid < NS) ? raw * c : -FLT_MAX;

        float mx = logit;
#pragma unroll
        for (int off = 16; off > 0; off >>= 1)
            mx = fmaxf(mx, __shfl_xor_sync(0xffffffffu, mx, off));

        float e = (tid < NS) ? expf(logit - mx) : 0.0f;
        float sum = e;
#pragma unroll
        for (int off = 16; off > 0; off >>= 1)
            sum += __shfl_xor_sync(0xffffffffu, sum, off);

        if (tid < NS) {
            out[q * NS + tid] = logit - mx - logf(sum);
            g_l2[q * NS + tid] = 0.0f;   // restore zero for next replay
        }
        if (tid == 0) g_cnt[q] = 0;
    }
}

// ---------------------------------------------------------------------------
extern "C" void kernel_launch(void* const* d_in, const int* in_sizes, int n_in,
                              void* d_out, int out_size) {
    const float* fm    = (const float*)d_in[0];  // (100, 640, 25) f32
    const float* w2    = (const float*)d_in[1];  // (25, 75, 25) f32
    const float* scale = (const float*)d_in[2];  // (1,) f32
    float* out = (float*)d_out;                  // (75, 25) f32

    fused_kernel<<<dim3(NCHUNK, NQ), 256>>>(fm, w2, scale, out);
}

// round 5
// speedup vs baseline: 1.0681x; 1.0681x over previous
#include <cuda_runtime.h>
#include <math.h>
#include <float.h>

// Problem constants
#define NS 25      // support count (WAY*SHOT)
#define NQ 75      // query count (WAY*QUERY_SHOT)
#define DD 640     // feature dim
#define MM 25      // M (inner dim)

// Scratch (device globals)
__device__ float g_P[NQ * NS * DD];   // P[q][s][d] = sum_m S[s,d,m]*W[s,q,m]
__device__ float g_l2[NQ * NS];       // raw sum_d (p-r)^2, [q][s]
__device__ int   g_cnt[NQ];           // softmax tickets per q

// ---------------------------------------------------------------------------
// Kernel 1: per-s GEMM. P[q][s][d] = sum_m W[s,q,m] * S[s,d,m]
// grid = (5 d-chunks of 128, 25 s), block = 256 (8 warps).
// Each warp: 10 q rows x 4 d (float4 per lane).
// Block (0,0) zeroes g_l2 / g_cnt for replay determinism.
// ---------------------------------------------------------------------------
__global__ __launch_bounds__(256) void k1_proj_support(
        const float* __restrict__ fm, const float* __restrict__ w2) {
    const int s  = blockIdx.y;
    const int d0 = blockIdx.x * 128;

    __shared__ __align__(16) float Wsm[MM][80];   // [m][q], q padded to 80
    __shared__ __align__(16) float Ssm[MM][132];  // [m][d], 128 d (+pad)

    const int tid = threadIdx.x;

    for (int idx = tid; idx < NQ * MM; idx += 256) {
        int q = idx / MM, m = idx - q * MM;
        Wsm[m][q] = w2[s * (NQ * MM) + idx];
    }
    for (int idx = tid; idx < 5 * MM; idx += 256) {       // zero-pad q=75..79
        int m = idx % MM, q = NQ + idx / MM;
        Wsm[m][q] = 0.0f;
    }
    for (int idx = tid; idx < 128 * MM; idx += 256) {
        int d = idx / MM, m = idx - d * MM;
        Ssm[m][d] = fm[s * (DD * MM) + d0 * MM + idx];
    }
    if (blockIdx.x == 0 && s == 0) {
        for (int i = tid; i < NQ * NS; i += 256) g_l2[i] = 0.0f;
        for (int i = tid; i < NQ; i += 256) g_cnt[i] = 0;
    }
    __syncthreads();

    const int lane = tid & 31;
    const int qb   = (tid >> 5) * 10;   // warp -> q base (0..70)

    float acc[10][4];
#pragma unroll
    for (int j = 0; j < 10; j++)
#pragma unroll
        for (int i = 0; i < 4; i++) acc[j][i] = 0.0f;

#pragma unroll
    for (int m = 0; m < MM; m++) {
        float4 bv = *reinterpret_cast<const float4*>(&Ssm[m][lane * 4]);
#pragma unroll
        for (int j = 0; j < 10; j++) {
            float a = Wsm[m][qb + j];
            acc[j][0] = fmaf(a, bv.x, acc[j][0]);
            acc[j][1] = fmaf(a, bv.y, acc[j][1]);
            acc[j][2] = fmaf(a, bv.z, acc[j][2]);
            acc[j][3] = fmaf(a, bv.w, acc[j][3]);
        }
    }

#pragma unroll
    for (int j = 0; j < 10; j++) {
        int q = qb + j;
        if (q < NQ) {
            float4 v = make_float4(acc[j][0], acc[j][1], acc[j][2], acc[j][3]);
            *reinterpret_cast<float4*>(&g_P[(q * NS + s) * DD + d0 + lane * 4]) = v;
        }
    }
}

// ---------------------------------------------------------------------------
// Kernel 2: per-(q, d-chunk) GEMM + fused L2 atomics + last-block softmax.
// grid = (5 d-chunks of 128, 75 q), block = 448 (14 warps).
// Each warp owns 2 s rows (28 >= 25); lanes own 4 d (float4).
// 5250 resident warps (~35/SM) vs 2625 before -> latency hiding.
// ---------------------------------------------------------------------------
__global__ __launch_bounds__(448) void k2_query_acc_softmax(
        const float* __restrict__ fm, const float* __restrict__ w2,
        const float* __restrict__ scale, float* __restrict__ out) {
    const int q  = blockIdx.y;
    const int d0 = blockIdx.x * 128;

    __shared__ __align__(16) float Wsm[MM][36];   // [m][s], s padded to 32
    __shared__ __align__(16) float Qsm[MM][132];  // [m][d], 128 d (+pad)
    __shared__ int s_last;

    const int tid = threadIdx.x;  // 448

    for (int idx = tid; idx < NS * MM; idx += 448) {
        int sI = idx / MM, m = idx - sI * MM;
        Wsm[m][sI] = w2[(sI * NQ + q) * MM + m];
    }
    for (int idx = tid; idx < 7 * MM; idx += 448) {       // zero-pad s=25..31
        int m = idx % MM, sI = NS + idx / MM;
        Wsm[m][sI] = 0.0f;
    }
    for (int idx = tid; idx < 128 * MM; idx += 448) {
        int d = idx / MM, m = idx - d * MM;
        Qsm[m][d] = fm[(NS + q) * (DD * MM) + d0 * MM + idx];
    }
    __syncthreads();

    const int lane = tid & 31;
    const int warp = tid >> 5;    // 0..13
    const int sb   = warp * 2;    // s base (0..26)

    float acc[2][4];
#pragma unroll
    for (int j = 0; j < 2; j++)
#pragma unroll
        for (int i = 0; i < 4; i++) acc[j][i] = 0.0f;

#pragma unroll
    for (int m = 0; m < MM; m++) {
        float4 bv = *reinterpret_cast<const float4*>(&Qsm[m][lane * 4]);
        float  a0 = Wsm[m][sb];
        float  a1 = Wsm[m][sb + 1];
        acc[0][0] = fmaf(a0, bv.x, acc[0][0]);
        acc[0][1] = fmaf(a0, bv.y, acc[0][1]);
        acc[0][2] = fmaf(a0, bv.z, acc[0][2]);
        acc[0][3] = fmaf(a0, bv.w, acc[0][3]);
        acc[1][0] = fmaf(a1, bv.x, acc[1][0]);
        acc[1][1] = fmaf(a1, bv.y, acc[1][1]);
        acc[1][2] = fmaf(a1, bv.z, acc[1][2]);
        acc[1][3] = fmaf(a1, bv.w, acc[1][3]);
    }

    // Epilogue: (r - p)^2, reduce 4 local + 32 lanes, atomic add into g_l2.
#pragma unroll
    for (int j = 0; j < 2; j++) {
        int   s    = sb + j;
        float part = 0.0f;
        if (s < NS) {
            float4 pv = *reinterpret_cast<const float4*>(
                &g_P[(q * NS + s) * DD + d0 + lane * 4]);
            float t0 = acc[j][0] - pv.x;
            float t1 = acc[j][1] - pv.y;
            float t2 = acc[j][2] - pv.z;
            float t3 = acc[j][3] - pv.w;
            part = t0 * t0 + t1 * t1 + t2 * t2 + t3 * t3;
        }
#pragma unroll
        for (int off = 16; off > 0; off >>= 1)
            part += __shfl_down_sync(0xffffffffu, part, off);
        if (lane == 0 && s < NS)
            atomicAdd(&g_l2[q * NS + s], part);
    }

    // Ticket: last of the 5 chunk-blocks for this q runs the softmax.
    __syncthreads();
    __threadfence();
    if (tid == 0)
        s_last = (atomicAdd(&g_cnt[q], 1) == 4) ? 1 : 0;
    __syncthreads();

    if (s_last && tid < 32) {
        __threadfence();  // acquire: other blocks' g_l2 adds visible
        const float c = -scale[0] / 312500.0f;  // 1/(M^2 * G*Q*Q*SHOT)
        float raw   = (tid < NS) ? __ldcg(&g_l2[q * NS + tid]) : 0.0f;
        float logit = (tid < NS) ? raw * c : -FLT_MAX;

        float mx = logit;
#pragma unroll
        for (int off = 16; off > 0; off >>= 1)
            mx = fmaxf(mx, __shfl_xor_sync(0xffffffffu, mx, off));

        float e = (tid < NS) ? expf(logit - mx) : 0.0f;
        float sum = e;
#pragma unroll
        for (int off = 16; off > 0; off >>= 1)
            sum += __shfl_xor_sync(0xffffffffu, sum, off);

        if (tid < NS)
            out[q * NS + tid] = logit - mx - logf(sum);
    }
}

// ---------------------------------------------------------------------------
extern "C" void kernel_launch(void* const* d_in, const int* in_sizes, int n_in,
                              void* d_out, int out_size) {
    const float* fm    = (const float*)d_in[0];  // (100, 640, 25) f32
    const float* w2    = (const float*)d_in[1];  // (25, 75, 25) f32
    const float* scale = (const float*)d_in[2];  // (1,) f32
    float* out = (float*)d_out;                  // (75, 25) f32

    k1_proj_support<<<dim3(5, 25), 256>>>(fm, w2);
    k2_query_acc_softmax<<<dim3(5, NQ), 448>>>(fm, w2, scale, out);
}

// round 6
// speedup vs baseline: 1.1441x; 1.0712x over previous
#include <cuda_runtime.h>
#include <math.h>
#include <float.h>

// Problem constants
#define NS 25      // support count (WAY*SHOT)
#define NQ 75      // query count (WAY*QUERY_SHOT)
#define DD 640     // feature dim
#define MM 25      // M (inner dim)

// Scratch (device globals)
__device__ float g_P[NQ * NS * DD];   // P[q][s][d] = sum_m S[s,d,m]*W[s,q,m]
__device__ float g_l2[NQ * NS];       // raw sum_d (p-r)^2, [q][s]
__device__ int   g_cnt[NQ];           // softmax tickets per q

// ---------------------------------------------------------------------------
// Kernel 1: per-s GEMM. P[q][s][d] = sum_m W[s,q,m] * S[s,d,m]
// grid = (5 d-chunks of 128, 25 s), block = 480 (15 warps).
// Each warp: 5 q rows x 4 d (float4 per lane) -> covers q 0..74 exactly.
// Block (0,0) zeroes g_l2 / g_cnt for replay determinism.
// ---------------------------------------------------------------------------
__global__ __launch_bounds__(480) void k1_proj_support(
        const float* __restrict__ fm, const float* __restrict__ w2) {
    const int s  = blockIdx.y;
    const int d0 = blockIdx.x * 128;

    __shared__ __align__(16) float Wsm[MM][76];   // [m][q], 75 q (+pad)
    __shared__ __align__(16) float Ssm[MM][132];  // [m][d], 128 d (+pad)

    const int tid = threadIdx.x;  // 480

    for (int idx = tid; idx < NQ * MM; idx += 480) {
        int q = idx / MM, m = idx - q * MM;
        Wsm[m][q] = w2[s * (NQ * MM) + idx];
    }
    for (int idx = tid; idx < 128 * MM; idx += 480) {
        int d = idx / MM, m = idx - d * MM;
        Ssm[m][d] = fm[s * (DD * MM) + d0 * MM + idx];
    }
    if (blockIdx.x == 0 && s == 0) {
        for (int i = tid; i < NQ * NS; i += 480) g_l2[i] = 0.0f;
        for (int i = tid; i < NQ; i += 480) g_cnt[i] = 0;
    }
    __syncthreads();

    const int lane = tid & 31;
    const int qb   = (tid >> 5) * 5;   // warp -> q base (0..70)

    float acc[5][4];
#pragma unroll
    for (int j = 0; j < 5; j++)
#pragma unroll
        for (int i = 0; i < 4; i++) acc[j][i] = 0.0f;

#pragma unroll
    for (int m = 0; m < MM; m++) {
        float4 bv = *reinterpret_cast<const float4*>(&Ssm[m][lane * 4]);
#pragma unroll
        for (int j = 0; j < 5; j++) {
            float a = Wsm[m][qb + j];
            acc[j][0] = fmaf(a, bv.x, acc[j][0]);
            acc[j][1] = fmaf(a, bv.y, acc[j][1]);
            acc[j][2] = fmaf(a, bv.z, acc[j][2]);
            acc[j][3] = fmaf(a, bv.w, acc[j][3]);
        }
    }

#pragma unroll
    for (int j = 0; j < 5; j++) {
        int q = qb + j;
        float4 v = make_float4(acc[j][0], acc[j][1], acc[j][2], acc[j][3]);
        *reinterpret_cast<float4*>(&g_P[(q * NS + s) * DD + d0 + lane * 4]) = v;
    }
}

// ---------------------------------------------------------------------------
// Kernel 2: per-(q, d-chunk) GEMM + fused L2 atomics + last-block softmax.
// grid = (5 d-chunks of 128, 75 q), block = 448 (14 warps).
// Each warp owns 2 s rows; lanes own 4 d (float4).
// g_P is prefetched at block entry (independent of the r-GEMM) so its
// ~250-600 cycle latency hides behind staging + the 25-iter main loop.
// ---------------------------------------------------------------------------
__global__ __launch_bounds__(448) void k2_query_acc_softmax(
        const float* __restrict__ fm, const float* __restrict__ w2,
        const float* __restrict__ scale, float* __restrict__ out) {
    const int q  = blockIdx.y;
    const int d0 = blockIdx.x * 128;

    __shared__ __align__(16) float Wsm[MM][36];   // [m][s], s padded to 32
    __shared__ __align__(16) float Qsm[MM][132];  // [m][d], 128 d (+pad)
    __shared__ int s_last;

    const int tid  = threadIdx.x;  // 448
    const int lane = tid & 31;
    const int warp = tid >> 5;     // 0..13
    const int sb   = warp * 2;     // s base (0..26), even

    // -------- Prefetch P for the epilogue (issued before any smem work) ----
    float4 pv0 = make_float4(0.f, 0.f, 0.f, 0.f);
    float4 pv1 = make_float4(0.f, 0.f, 0.f, 0.f);
    if (sb < NS)
        pv0 = *reinterpret_cast<const float4*>(
            &g_P[(q * NS + sb) * DD + d0 + lane * 4]);
    if (sb + 1 < NS)
        pv1 = *reinterpret_cast<const float4*>(
            &g_P[(q * NS + sb + 1) * DD + d0 + lane * 4]);

    // -------- Stage W[:,q,:] and Q[q, chunk, :] ----------------------------
    for (int idx = tid; idx < NS * MM; idx += 448) {
        int sI = idx / MM, m = idx - sI * MM;
        Wsm[m][sI] = w2[(sI * NQ + q) * MM + m];
    }
    for (int idx = tid; idx < 7 * MM; idx += 448) {       // zero-pad s=25..31
        int m = idx % MM, sI = NS + idx / MM;
        Wsm[m][sI] = 0.0f;
    }
    for (int idx = tid; idx < 128 * MM; idx += 448) {
        int d = idx / MM, m = idx - d * MM;
        Qsm[m][d] = fm[(NS + q) * (DD * MM) + d0 * MM + idx];
    }
    __syncthreads();

    float acc[2][4];
#pragma unroll
    for (int j = 0; j < 2; j++)
#pragma unroll
        for (int i = 0; i < 4; i++) acc[j][i] = 0.0f;

#pragma unroll
    for (int m = 0; m < MM; m++) {
        float4 bv = *reinterpret_cast<const float4*>(&Qsm[m][lane * 4]);
        float2 av = *reinterpret_cast<const float2*>(&Wsm[m][sb]);  // LDS.64
        acc[0][0] = fmaf(av.x, bv.x, acc[0][0]);
        acc[0][1] = fmaf(av.x, bv.y, acc[0][1]);
        acc[0][2] = fmaf(av.x, bv.z, acc[0][2]);
        acc[0][3] = fmaf(av.x, bv.w, acc[0][3]);
        acc[1][0] = fmaf(av.y, bv.x, acc[1][0]);
        acc[1][1] = fmaf(av.y, bv.y, acc[1][1]);
        acc[1][2] = fmaf(av.y, bv.z, acc[1][2]);
        acc[1][3] = fmaf(av.y, bv.w, acc[1][3]);
    }

    // -------- Epilogue: (r - p)^2, lane reduce, atomic add -----------------
    {
        float t0 = acc[0][0] - pv0.x;
        float t1 = acc[0][1] - pv0.y;
        float t2 = acc[0][2] - pv0.z;
        float t3 = acc[0][3] - pv0.w;
        float part = t0 * t0 + t1 * t1 + t2 * t2 + t3 * t3;
#pragma unroll
        for (int off = 16; off > 0; off >>= 1)
            part += __shfl_down_sync(0xffffffffu, part, off);
        if (lane == 0 && sb < NS)
            atomicAdd(&g_l2[q * NS + sb], part);
    }
    {
        float t0 = acc[1][0] - pv1.x;
        float t1 = acc[1][1] - pv1.y;
        float t2 = acc[1][2] - pv1.z;
        float t3 = acc[1][3] - pv1.w;
        float part = t0 * t0 + t1 * t1 + t2 * t2 + t3 * t3;
#pragma unroll
        for (int off = 16; off > 0; off >>= 1)
            part += __shfl_down_sync(0xffffffffu, part, off);
        if (lane == 0 && sb + 1 < NS)
            atomicAdd(&g_l2[q * NS + sb + 1], part);
    }

    // -------- Ticket: last of 5 chunk-blocks for this q runs softmax -------
    __syncthreads();
    __threadfence();
    if (tid == 0)
        s_last = (atomicAdd(&g_cnt[q], 1) == 4) ? 1 : 0;
    __syncthreads();

    if (s_last && tid < 32) {
        __threadfence();  // acquire: other blocks' g_l2 adds visible
        const float c = -scale[0] / 312500.0f;  // 1/(M^2 * G*Q*Q*SHOT)
        float raw   = (tid < NS) ? __ldcg(&g_l2[q * NS + tid]) : 0.0f;
        float logit = (tid < NS) ? raw * c : -FLT_MAX;

        float mx = logit;
#pragma unroll
        for (int off = 16; off > 0; off >>= 1)
            mx = fmaxf(mx, __shfl_xor_sync(0xffffffffu, mx, off));

        float e = (tid < NS) ? expf(logit - mx) : 0.0f;
        float sum = e;
#pragma unroll
        for (int off = 16; off > 0; off >>= 1)
            sum += __shfl_xor_sync(0xffffffffu, sum, off);

        if (tid < NS)
            out[q * NS + tid] = logit - mx - logf(sum);
    }
}

// ---------------------------------------------------------------------------
extern "C" void kernel_launch(void* const* d_in, const int* in_sizes, int n_in,
                              void* d_out, int out_size) {
    const float* fm    = (const float*)d_in[0];  // (100, 640, 25) f32
    const float* w2    = (const float*)d_in[1];  // (25, 75, 25) f32
    const float* scale = (const float*)d_in[2];  // (1,) f32
    float* out = (float*)d_out;                  // (75, 25) f32

    k1_proj_support<<<dim3(5, 25), 480>>>(fm, w2);
    k2_query_acc_softmax<<<dim3(5, NQ), 448>>>(fm, w2, scale, out);
}